// round 8
// baseline (speedup 1.0000x reference)
#include <cuda_runtime.h>
#include <cuda_bf16.h>
#include <cstdint>

#define Bb  2
#define Pp  128
#define Cc  8
#define Hh  16
#define Gg  4
#define Dd  64
#define Ee  1024
#define EKVv 256
#define Tt  1024

// ---------------- scratch (device globals; no allocation allowed) -----------
__device__ __align__(16) float g_q[Bb*Tt*Ee];
__device__ __align__(16) float g_kv[Bb*Tt*2*EKVv];
__device__ __align__(16) float g_tk[Pp*EKVv];
__device__ __align__(16) float g_ck[Cc*EKVv];
__device__ __align__(16) float g_time[Bb*Hh*Tt*Pp];
__device__ __align__(16) float g_chan[Bb*Hh*Tt*Cc];
__device__ __align__(16) float g_ao[Bb*Tt*Ee];

// bf16 hi/lo planes for tensor GEMMs (weights stored transposed: [N][K])
__device__ __align__(16) __nv_bfloat16 g_hs_h[Bb*Tt*Ee];
__device__ __align__(16) __nv_bfloat16 g_hs_l[Bb*Tt*Ee];
__device__ __align__(16) __nv_bfloat16 g_ao_h[Bb*Tt*Ee];
__device__ __align__(16) __nv_bfloat16 g_ao_l[Bb*Tt*Ee];
__device__ __align__(16) __nv_bfloat16 g_WqT_h[Ee*Ee];
__device__ __align__(16) __nv_bfloat16 g_WqT_l[Ee*Ee];
__device__ __align__(16) __nv_bfloat16 g_WkvT_h[2*EKVv*Ee];
__device__ __align__(16) __nv_bfloat16 g_WkvT_l[2*EKVv*Ee];
__device__ __align__(16) __nv_bfloat16 g_WpT_h[Ee*Ee];
__device__ __align__(16) __nv_bfloat16 g_WpT_l[Ee*Ee];

#define SMEM_SWIZ(b) ((b) ^ (((b) >> 3) & 0x70))

__device__ __forceinline__ uint32_t smem_u32(const void* p) {
    uint32_t a;
    asm("{ .reg .u64 t; cvta.to.shared.u64 t, %1; cvt.u32.u64 %0, t; }"
        : "=r"(a) : "l"(p));
    return a;
}
__device__ __forceinline__ void ldm_x4(uint32_t addr, uint32_t& r0, uint32_t& r1,
                                       uint32_t& r2, uint32_t& r3) {
    asm volatile("ldmatrix.sync.aligned.m8n8.x4.shared.b16 {%0,%1,%2,%3}, [%4];"
                 : "=r"(r0), "=r"(r1), "=r"(r2), "=r"(r3) : "r"(addr));
}
#define MMA16816(d, a, b0, b1)                                              \
    asm volatile("mma.sync.aligned.m16n8k16.row.col.f32.bf16.bf16.f32 "     \
        "{%0,%1,%2,%3}, {%4,%5,%6,%7}, {%8,%9}, {%0,%1,%2,%3};"             \
        : "+f"((d)[0]), "+f"((d)[1]), "+f"((d)[2]), "+f"((d)[3])            \
        : "r"((a)[0]), "r"((a)[1]), "r"((a)[2]), "r"((a)[3]),               \
          "r"(b0), "r"(b1))

__device__ __forceinline__ void bf16_split(float x, __nv_bfloat16& h, __nv_bfloat16& l) {
    h = __float2bfloat16(x);
    l = __float2bfloat16(x - __bfloat162float(h));
}

// ---------------- pre-convert: hs planes + W^T planes -------------------------
// blocks: [0,512) hs | [512,1536) WqT | [1536,2048) WkvT | [2048,3072) WpT
__global__ __launch_bounds__(256) void preconv_kernel(
        const float* __restrict__ hs, const float* __restrict__ Wq,
        const float* __restrict__ Wkv, const float* __restrict__ Wp) {
    __shared__ float s[32][33];
    int blk = blockIdx.x, tid = threadIdx.x;
    if (blk < 512) {
        const float4* src = (const float4*)hs;
#pragma unroll
        for (int j = 0; j < 4; j++) {
            int f4 = blk * 1024 + j * 256 + tid;
            float4 v = src[f4];
            __nv_bfloat16 hx, lx, hy, ly, hz, lz, hw, lw;
            bf16_split(v.x, hx, lx); bf16_split(v.y, hy, ly);
            bf16_split(v.z, hz, lz); bf16_split(v.w, hw, lw);
            ((__nv_bfloat162*)g_hs_h)[f4 * 2 + 0] = __nv_bfloat162(hx, hy);
            ((__nv_bfloat162*)g_hs_h)[f4 * 2 + 1] = __nv_bfloat162(hz, hw);
            ((__nv_bfloat162*)g_hs_l)[f4 * 2 + 0] = __nv_bfloat162(lx, ly);
            ((__nv_bfloat162*)g_hs_l)[f4 * 2 + 1] = __nv_bfloat162(lz, lw);
        }
        return;
    }
    const float* W; __nv_bfloat16 *Th, *Tl; int N, t;
    if (blk < 1536)      { W = Wq;  Th = g_WqT_h;  Tl = g_WqT_l;  N = 1024; t = blk - 512; }
    else if (blk < 2048) { W = Wkv; Th = g_WkvT_h; Tl = g_WkvT_l; N = 512;  t = blk - 1536; }
    else                 { W = Wp;  Th = g_WpT_h;  Tl = g_WpT_l;  N = 1024; t = blk - 2048; }
    int nt = N / 32;
    int k0 = (t / nt) * 32, n0 = (t % nt) * 32;
    int tx = tid & 31, ty = tid >> 5;
#pragma unroll
    for (int i = 0; i < 4; i++) {
        int r = ty + i * 8;
        s[r][tx] = W[(size_t)(k0 + r) * N + n0 + tx];
    }
    __syncthreads();
#pragma unroll
    for (int i = 0; i < 4; i++) {
        int r = ty + i * 8;
        float v = s[tx][r];                 // = W[k0+tx][n0+r]
        __nv_bfloat16 h, l; bf16_split(v, h, l);
        Th[(size_t)(n0 + r) * 1024 + k0 + tx] = h;
        Tl[(size_t)(n0 + r) * 1024 + k0 + tx] = l;
    }
}

// ---------------- ao -> planes ------------------------------------------------
__global__ __launch_bounds__(256) void conv_ao_kernel() {
    int blk = blockIdx.x, tid = threadIdx.x;
    const float4* src = (const float4*)g_ao;
#pragma unroll
    for (int j = 0; j < 4; j++) {
        int f4 = blk * 1024 + j * 256 + tid;
        float4 v = src[f4];
        __nv_bfloat16 hx, lx, hy, ly, hz, lz, hw, lw;
        bf16_split(v.x, hx, lx); bf16_split(v.y, hy, ly);
        bf16_split(v.z, hz, lz); bf16_split(v.w, hw, lw);
        ((__nv_bfloat162*)g_ao_h)[f4 * 2 + 0] = __nv_bfloat162(hx, hy);
        ((__nv_bfloat162*)g_ao_h)[f4 * 2 + 1] = __nv_bfloat162(hz, hw);
        ((__nv_bfloat162*)g_ao_l)[f4 * 2 + 0] = __nv_bfloat162(lx, ly);
        ((__nv_bfloat162*)g_ao_l)[f4 * 2 + 1] = __nv_bfloat162(lz, lw);
    }
}

// ---------------- bf16-split GEMM via mma.sync (HMMA) -------------------------
// C[m0:+128, n0:+128] = (Ah+Al)(Bh+Bl)^T.  A: [M][1024] bf16 planes,
// B: [N][1024] bf16 planes (i.e. W^T, K-contiguous).  256 threads, 8 warps,
// warp tile 32x64.  smem: 4 planes x 128 rows x 128B (SW128-swizzled) = 64KB.
static constexpr int TG_SMEM = 65536;

// ldmatrix lane-address helpers (x4 quads, same swizzle as the store)
__device__ __forceinline__ uint32_t a_addr(uint32_t base, int mrow, int koB, int lane) {
    int q = lane >> 3, ri = lane & 7;
    int row = mrow + (q & 1) * 8 + ri;
    int col = koB + (q >> 1) * 16;
    return base + SMEM_SWIZ(row * 128 + col);
}
__device__ __forceinline__ uint32_t b_addr(uint32_t base, int nrow, int koB, int lane) {
    int q = lane >> 3, ri = lane & 7;
    int row = nrow + (q >> 1) * 8 + ri;
    int col = koB + (q & 1) * 16;
    return base + SMEM_SWIZ(row * 128 + col);
}

__device__ void tgemm_body(const __nv_bfloat16* __restrict__ Ah,
                           const __nv_bfloat16* __restrict__ Al,
                           const __nv_bfloat16* __restrict__ Bh,
                           const __nv_bfloat16* __restrict__ Bl,
                           float* __restrict__ C, int ldc, int m0, int n0,
                           char* smem) {
    uint32_t sb = smem_u32(smem);
    int tid = threadIdx.x, wid = tid >> 5, lane = tid & 31;
    int wm = (wid & 3) * 32;        // warp rows within tile
    int wn = (wid >> 2) * 64;       // warp cols within tile
    const int SA_H = 0, SA_L = 16384, SB_H = 32768, SB_L = 49152;

    float acc[2][8][4];
#pragma unroll
    for (int mt = 0; mt < 2; mt++)
#pragma unroll
        for (int nt = 0; nt < 8; nt++)
#pragma unroll
            for (int e = 0; e < 4; e++) acc[mt][nt][e] = 0.f;

    for (int kc = 0; kc < 16; kc++) {
        // stage 4 planes x 128 rows x 128B (cols kc*64 bf16)
        for (int i = tid; i < 4096; i += 256) {
            int p = i >> 10, rem = i & 1023, r = rem >> 3, u = rem & 7;
            const char* src; int sbase;
            if (p == 0)      { src = (const char*)Ah + (size_t)(m0 + r) * 2048; sbase = SA_H; }
            else if (p == 1) { src = (const char*)Al + (size_t)(m0 + r) * 2048; sbase = SA_L; }
            else if (p == 2) { src = (const char*)Bh + (size_t)(n0 + r) * 2048; sbase = SB_H; }
            else             { src = (const char*)Bl + (size_t)(n0 + r) * 2048; sbase = SB_L; }
            uint4 v = *(const uint4*)(src + kc * 128 + u * 16);
            *(uint4*)(smem + sbase + SMEM_SWIZ(r * 128 + u * 16)) = v;
        }
        __syncthreads();

#pragma unroll
        for (int ks = 0; ks < 4; ks++) {        // 4 x k16 per 64-col chunk
            int koB = ks * 32;
            uint32_t ah[2][4], al[2][4], bh[4][4], bl[4][4];
#pragma unroll
            for (int mt = 0; mt < 2; mt++) {
                ldm_x4(a_addr(sb + SA_H, wm + mt * 16, koB, lane),
                       ah[mt][0], ah[mt][1], ah[mt][2], ah[mt][3]);
                ldm_x4(a_addr(sb + SA_L, wm + mt * 16, koB, lane),
                       al[mt][0], al[mt][1], al[mt][2], al[mt][3]);
            }
#pragma unroll
            for (int j = 0; j < 4; j++) {
                ldm_x4(b_addr(sb + SB_H, wn + j * 16, koB, lane),
                       bh[j][0], bh[j][1], bh[j][2], bh[j][3]);
                ldm_x4(b_addr(sb + SB_L, wn + j * 16, koB, lane),
                       bl[j][0], bl[j][1], bl[j][2], bl[j][3]);
            }
#pragma unroll
            for (int mt = 0; mt < 2; mt++)
#pragma unroll
                for (int nt = 0; nt < 8; nt++) {
                    int j = nt >> 1, o = (nt & 1) * 2;
                    MMA16816(acc[mt][nt], ah[mt], bh[j][o], bh[j][o + 1]);
                    MMA16816(acc[mt][nt], ah[mt], bl[j][o], bl[j][o + 1]);
                    MMA16816(acc[mt][nt], al[mt], bh[j][o], bh[j][o + 1]);
                }
        }
        __syncthreads();
    }

    // epilogue: d0,d1 -> (row g, col 2*tig), d2,d3 -> (row g+8)
    int g = lane >> 2, tig = lane & 3;
#pragma unroll
    for (int mt = 0; mt < 2; mt++)
#pragma unroll
        for (int nt = 0; nt < 8; nt++) {
            int row = m0 + wm + mt * 16 + g;
            int col = n0 + wn + nt * 8 + tig * 2;
            *(float2*)&C[(size_t)row * ldc + col] =
                make_float2(acc[mt][nt][0], acc[mt][nt][1]);
            *(float2*)&C[(size_t)(row + 8) * ldc + col] =
                make_float2(acc[mt][nt][2], acc[mt][nt][3]);
        }
}

// blocks: [0,128) q tiles | [128,192) kv tiles
__global__ __launch_bounds__(256) void tgemm_qkv(float* __restrict__ q,
                                                 float* __restrict__ kv) {
    extern __shared__ char smem[];
    int blk = blockIdx.x;
    if (blk < 128) {
        tgemm_body(g_hs_h, g_hs_l, g_WqT_h, g_WqT_l, q, Ee,
                   (blk >> 3) * 128, (blk & 7) * 128, smem);
    } else {
        int b = blk - 128;
        tgemm_body(g_hs_h, g_hs_l, g_WkvT_h, g_WkvT_l, kv, 2 * EKVv,
                   (b >> 2) * 128, (b & 3) * 128, smem);
    }
}

__global__ __launch_bounds__(256) void tgemm_proj(float* __restrict__ out) {
    extern __shared__ char smem[];
    int blk = blockIdx.x;
    tgemm_body(g_ao_h, g_ao_l, g_WpT_h, g_WpT_l, out, Ee,
               (blk >> 3) * 128, (blk & 7) * 128, smem);
}

// ---------------- skinny GEMMs (tk, ck) ---------------------------------------
__device__ __forceinline__ void skinny_body(
        const float* __restrict__ A, const float* __restrict__ B,
        float* __restrict__ C, int N, int K, int m, int n0) {
    __shared__ float red[128];
    int t = threadIdx.x;
    int n = n0 + (t & 127);
    int kc = t >> 7;
    int kh = K >> 1;
    const float* a = A + (size_t)m * K + kc * kh;
    const float* b = B + (size_t)(kc * kh) * N + n;
    float acc = 0.f;
#pragma unroll 8
    for (int k = 0; k < kh; k++) acc += a[k] * b[(size_t)k * N];
    if (kc) red[t & 127] = acc;
    __syncthreads();
    if (!kc) C[(size_t)m * N + n] = acc + red[t & 127];
}

__global__ __launch_bounds__(256) void skinny_launch(
        const float* __restrict__ pe, const float* __restrict__ Wpos,
        const float* __restrict__ ce, const float* __restrict__ Wchan,
        float* __restrict__ tk, float* __restrict__ ck) {
    int blk = blockIdx.x;
    if (blk < 256) skinny_body(pe, Wpos, tk, EKVv, Ee, blk >> 1, (blk & 1) * 128);
    else { int b = blk - 256; skinny_body(ce, Wchan, ck, EKVv, Ee, b >> 1, (b & 1) * 128); }
}

// ---------------- merged time_att + chan_att ---------------------------------
__global__ __launch_bounds__(256) void rel_att_kernel(
        const float* __restrict__ q, const float* __restrict__ bias) {
    __shared__ float qs[32][65];
    __shared__ float ks[128][64];
    int blk = blockIdx.x;
    int tid = threadIdx.x;
    if (blk < 1024) {
        int bh = blk & 31;
        int b = bh / Hh, h = bh % Hh, kvh = h / Gg;
        int t0 = (blk >> 5) * 32;
        for (int i = tid; i < 32 * 64; i += 256) {
            int r = i >> 6, d = i & 63;
            qs[r][d] = q[((size_t)(b * Tt + t0 + r)) * Ee + h * Dd + d]
                     + bias[EKVv + kvh * Dd + d];
        }
        for (int i = tid; i < 128 * 64; i += 256) {
            int p = i >> 6, d = i & 63;
            ks[p][d] = g_tk[p * EKVv + kvh * Dd + d];
        }
        __syncthreads();
        int r = tid & 31;
        int pb = (tid >> 5) * 16;
        float acc[16];
#pragma unroll
        for (int j = 0; j < 16; j++) acc[j] = 0.f;
        for (int d = 0; d < 64; d++) {
            float qv = qs[r][d];
#pragma unroll
            for (int j = 0; j < 16; j++) acc[j] += qv * ks[pb + j][d];
        }
        float* dst = g_time + ((size_t)bh * Tt + t0 + r) * Pp + pb;
#pragma unroll
        for (int j = 0; j < 16; j++) dst[j] = acc[j];
    } else {
        int bc = blk - 1024;
        int bh = bc & 31;
        int b = bh / Hh, h = bh % Hh, kvh = h / Gg;
        int t0 = (bc >> 5) * 32;
        for (int i = tid; i < 32 * 64; i += 256) {
            int r = i >> 6, d = i & 63;
            qs[r][d] = q[((size_t)(b * Tt + t0 + r)) * Ee + h * Dd + d]
                     + bias[2 * EKVv + kvh * Dd + d];
        }
        for (int i = tid; i < 8 * 64; i += 256) {
            int c = i >> 6, d = i & 63;
            ks[c][d] = g_ck[c * EKVv + kvh * Dd + d];
        }
        __syncthreads();
        int r = tid >> 3, c = tid & 7;
        float acc = 0.f;
#pragma unroll
        for (int d = 0; d < 64; d++) acc += qs[r][d] * ks[c][d];
        g_chan[((size_t)bh * Tt + t0 + r) * Cc + c] = acc;
    }
}

// ---------------- attention core: one block per (b, h, pt) -------------------
__global__ __launch_bounds__(256) void attn_kernel(
        const float* __restrict__ q, const float* __restrict__ bias) {
    __shared__ float qg[8][65];
    __shared__ float lg[8][1025];
    __shared__ float rinv[8];
    __shared__ float sred[8][8][64];
    int blk = blockIdx.x;
    int pt = blk % Pp;
    int h  = (blk / Pp) % Hh;
    int b  = blk / (Pp * Hh);
    int kvh = h / Gg;
    int tid = threadIdx.x;
    int t0 = pt * Cc;

    for (int i = tid; i < 8 * 64; i += 256) {
        int c = i >> 6, d = i & 63;
        qg[c][d] = q[((size_t)(b * Tt + t0 + c)) * Ee + h * Dd + d]
                 + bias[kvh * Dd + d];
    }
    __syncthreads();

    int S = (pt + 1) * Cc;
    const float* tbase = g_time + (size_t)(b * Hh + h) * Tt * Pp;
    const float* cbase = g_chan + (size_t)(b * Hh + h) * Tt * Cc;

    for (int idx = tid; idx < S * 8; idx += 256) {
        int s = idx >> 3, c = idx & 7;
        int t = t0 + c;
        int ps = s >> 3, cs = s & 7;
        unsigned m = (unsigned)(t + 1) * Pp + ps;
        unsigned i2 = m / (Tt + 1);
        float tv = 0.f;
        if (m - i2 * (Tt + 1) != 0) tv = tbase[m - i2 - 1];
        int dc = c - cs; dc = dc < 0 ? -dc : dc;
        float cv = cbase[t * Cc + (Cc - 1 - dc)];
        lg[c][s] = tv + cv;
    }
    __syncthreads();

    int gLow = (pt == Pp - 1) ? 0 : ((pt > 10 ? pt - 10 : 0) * Cc);
    int nG = (S - gLow) * 8;
    for (int idx = tid; idx < nG; idx += 256) {
        int s = gLow + (idx >> 3);
        int c = idx & 7;
        const float4* gk4 = (const float4*)(g_kv
            + ((size_t)(b * Tt + s)) * (2 * EKVv) + kvh * Dd);
        float acc = 0.f;
#pragma unroll
        for (int d4 = 0; d4 < 16; d4++) {
            float4 gv = gk4[d4];
            acc += qg[c][d4 * 4 + 0] * gv.x + qg[c][d4 * 4 + 1] * gv.y
                 + qg[c][d4 * 4 + 2] * gv.z + qg[c][d4 * 4 + 3] * gv.w;
        }
        lg[c][s] += acc;
    }
    __syncthreads();

    int w = tid >> 5, lane = tid & 31;
    {
        float mx = -1e30f;
        for (int s = lane; s < S; s += 32) mx = fmaxf(mx, lg[w][s] * 0.125f);
#pragma unroll
        for (int o = 16; o > 0; o >>= 1)
            mx = fmaxf(mx, __shfl_xor_sync(0xffffffffu, mx, o));
        float sum = 0.f;
        for (int s = lane; s < S; s += 32) {
            float e = __expf(lg[w][s] * 0.125f - mx);
            lg[w][s] = e;
            sum += e;
        }
#pragma unroll
        for (int o = 16; o > 0; o >>= 1)
            sum += __shfl_xor_sync(0xffffffffu, sum, o);
        if (lane == 0) rinv[w] = 1.f / sum;
    }
    __syncthreads();

    {
        int dp = (tid & 31) * 2;
        int sg = tid >> 5;
        const float* vbase = g_kv + (size_t)b * Tt * (2 * EKVv) + EKVv
                           + kvh * Dd + dp;
        float accx[8], accy[8];
#pragma unroll
        for (int c = 0; c < 8; c++) { accx[c] = 0.f; accy[c] = 0.f; }
        for (int s = sg; s < S; s += 8) {
            float2 vv = *(const float2*)(vbase + (size_t)s * (2 * EKVv));
#pragma unroll
            for (int c = 0; c < 8; c++) {
                float wgt = lg[c][s];
                accx[c] += wgt * vv.x;
                accy[c] += wgt * vv.y;
            }
        }
#pragma unroll
        for (int c = 0; c < 8; c++) {
            sred[sg][c][dp]     = accx[c];
            sred[sg][c][dp + 1] = accy[c];
        }
    }
    __syncthreads();
    for (int i = tid; i < 512; i += 256) {
        int c = i >> 6, dd = i & 63;
        float o = ((sred[0][c][dd] + sred[1][c][dd])
                 + (sred[2][c][dd] + sred[3][c][dd]))
                + ((sred[4][c][dd] + sred[5][c][dd])
                 + (sred[6][c][dd] + sred[7][c][dd]));
        g_ao[((size_t)(b * Tt + t0 + c)) * Ee + h * Dd + dd] = o * rinv[c];
    }
}

// ---------------- launch ----------------------------------------------------
extern "C" void kernel_launch(void* const* d_in, const int* in_sizes, int n_in,
                              void* d_out, int out_size) {
    const float* hs    = (const float*)d_in[0];
    const float* pe    = (const float*)d_in[1];
    const float* ce    = (const float*)d_in[2];
    const float* Wq    = (const float*)d_in[3];
    const float* Wkv   = (const float*)d_in[4];
    const float* Wpos  = (const float*)d_in[5];
    const float* Wchan = (const float*)d_in[6];
    const float* Wproj = (const float*)d_in[7];
    const float* bias  = (const float*)d_in[8];

    float *q, *kv, *tk, *ck;
    cudaGetSymbolAddress((void**)&q,  g_q);
    cudaGetSymbolAddress((void**)&kv, g_kv);
    cudaGetSymbolAddress((void**)&tk, g_tk);
    cudaGetSymbolAddress((void**)&ck, g_ck);

    cudaFuncSetAttribute(tgemm_qkv, cudaFuncAttributeMaxDynamicSharedMemorySize, TG_SMEM);
    cudaFuncSetAttribute(tgemm_proj, cudaFuncAttributeMaxDynamicSharedMemorySize, TG_SMEM);

    // conversions (hs planes + transposed weight planes) and skinny GEMMs
    preconv_kernel<<<3072, 256>>>(hs, Wq, Wkv, Wproj);
    skinny_launch<<<272, 256>>>(pe, Wpos, ce, Wchan, tk, ck);

    // q + kv tensor-core GEMMs (HMMA bf16 split)
    tgemm_qkv<<<192, 256, TG_SMEM>>>(q, kv);

    // relative logits
    rel_att_kernel<<<2048, 256>>>(q, bias);

    // attention core
    attn_kernel<<<Bb * Hh * Pp, 256>>>(q, bias);

    // output projection
    conv_ao_kernel<<<512, 256>>>();
    tgemm_proj<<<128, 256, TG_SMEM>>>((float*)d_out);
}

// round 9
// speedup vs baseline: 1.1271x; 1.1271x over previous
#include <cuda_runtime.h>

#define Bb  2
#define Pp  128
#define Cc  8
#define Hh  16
#define Gg  4
#define Dd  64
#define Ee  1024
#define EKVv 256
#define Tt  1024

// ---------------- scratch (device globals; no allocation allowed) -----------
__device__ __align__(16) float g_q[Bb*Tt*Ee];
__device__ __align__(16) float g_kv[Bb*Tt*2*EKVv];
__device__ __align__(16) float g_tk[Pp*EKVv];
__device__ __align__(16) float g_ck[Cc*EKVv];
__device__ __align__(16) float g_time[Bb*Hh*Tt*Pp];
__device__ __align__(16) float g_chan[Bb*Hh*Tt*Cc];
__device__ __align__(16) float g_ao[Bb*Tt*Ee];

// ---------------- packed f32x2 helpers (sm_100+ PTX) -------------------------
__device__ __forceinline__ unsigned long long dup2(float x) {
    unsigned long long r;
    asm("mov.b64 %0, {%1, %1};" : "=l"(r) : "f"(x));
    return r;
}
__device__ __forceinline__ void fma2(unsigned long long& d,
                                     unsigned long long a, unsigned long long b) {
    asm("fma.rn.f32x2 %0, %1, %2, %0;" : "+l"(d) : "l"(a), "l"(b));
}

// ---------------- 128x128 fp32 GEMM tile body (8x8/thread, FMA2) -------------
__device__ __forceinline__ void gemm128_body(
        const float* __restrict__ A, const float* __restrict__ B,
        float* __restrict__ Cmat, int N, int K, int m0, int n0,
        float (*As)[8][128], float (*Bs)[8][128]) {
    int tid = threadIdx.x;
    int tx = tid & 15, ty = tid >> 4;
    int arow = tid >> 1, akq = (tid & 1) * 4;
    int brow = tid >> 5, bnq = (tid & 31) * 4;

    const float* Aptr = A + (size_t)(m0 + arow) * K + akq;
    const float* Bptr = B + (size_t)brow * N + n0 + bnq;

    unsigned long long acc2[8][4];
#pragma unroll
    for (int i = 0; i < 8; i++)
#pragma unroll
        for (int j = 0; j < 4; j++) acc2[i][j] = 0ull;

    float4 av = *(const float4*)Aptr;
    float4 bv = *(const float4*)Bptr;
    As[0][akq + 0][arow] = av.x;
    As[0][akq + 1][arow] = av.y;
    As[0][akq + 2][arow] = av.z;
    As[0][akq + 3][arow] = av.w;
    *(float4*)&Bs[0][brow][bnq] = bv;
    __syncthreads();

    int NT = K >> 3;
    int cur = 0;
    for (int kt = 0; kt < NT; kt++) {
        if (kt + 1 < NT) {
            av = *(const float4*)(Aptr + (kt + 1) * 8);
            bv = *(const float4*)(Bptr + (size_t)(kt + 1) * 8 * N);
        }
#pragma unroll
        for (int k = 0; k < 8; k++) {
            float4 a0 = *(const float4*)&As[cur][k][ty * 8];
            float4 a1 = *(const float4*)&As[cur][k][ty * 8 + 4];
            ulonglong2 bl0 = *(const ulonglong2*)&Bs[cur][k][tx * 8];
            ulonglong2 bl1 = *(const ulonglong2*)&Bs[cur][k][tx * 8 + 4];
            float ra[8] = {a0.x, a0.y, a0.z, a0.w, a1.x, a1.y, a1.z, a1.w};
            unsigned long long rb2[4] = {bl0.x, bl0.y, bl1.x, bl1.y};
#pragma unroll
            for (int i = 0; i < 8; i++) {
                unsigned long long a2 = dup2(ra[i]);
#pragma unroll
                for (int j = 0; j < 4; j++) fma2(acc2[i][j], a2, rb2[j]);
            }
        }
        if (kt + 1 < NT) {
            int nxt = cur ^ 1;
            As[nxt][akq + 0][arow] = av.x;
            As[nxt][akq + 1][arow] = av.y;
            As[nxt][akq + 2][arow] = av.z;
            As[nxt][akq + 3][arow] = av.w;
            *(float4*)&Bs[nxt][brow][bnq] = bv;
            __syncthreads();
            cur = nxt;
        }
    }

#pragma unroll
    for (int i = 0; i < 8; i++) {
        float* crow = Cmat + (size_t)(m0 + ty * 8 + i) * N + n0 + tx * 8;
        *(ulonglong2*)crow       = make_ulonglong2(acc2[i][0], acc2[i][1]);
        *(ulonglong2*)(crow + 4) = make_ulonglong2(acc2[i][2], acc2[i][3]);
    }
}

// ---------------- skinny row GEMM: C[m, n0:+128], intra-block split-K --------
__device__ __forceinline__ void skinny_body(
        const float* __restrict__ A, const float* __restrict__ B,
        float* __restrict__ C, int N, int K, int m, int n0) {
    __shared__ float red[128];
    int t = threadIdx.x;
    int n = n0 + (t & 127);
    int kc = t >> 7;
    int kh = K >> 1;
    const float* a = A + (size_t)m * K + kc * kh;
    const float* b = B + (size_t)(kc * kh) * N + n;
    float acc = 0.f;
#pragma unroll 8
    for (int k = 0; k < kh; k++) acc += a[k] * b[(size_t)k * N];
    if (kc) red[t & 127] = acc;
    __syncthreads();
    if (!kc) C[(size_t)m * N + n] = acc + red[t & 127];
}

// ---------------- one launch for ALL projections ------------------------------
// blocks: [0,128) q | [128,192) kv | [192,448) tk | [448,464) ck
__global__ __launch_bounds__(256) void mega_gemm(
        const float* __restrict__ hs, const float* __restrict__ Wq,
        const float* __restrict__ Wkv,
        const float* __restrict__ pe, const float* __restrict__ Wpos,
        const float* __restrict__ ce, const float* __restrict__ Wchan,
        float* __restrict__ q, float* __restrict__ kv,
        float* __restrict__ tk, float* __restrict__ ck) {
    __shared__ float As[2][8][128];
    __shared__ float Bs[2][8][128];
    int blk = blockIdx.x;
    if (blk < 128) {
        gemm128_body(hs, Wq, q, Ee, Ee, (blk >> 3) * 128, (blk & 7) * 128, As, Bs);
    } else if (blk < 192) {
        int b = blk - 128;
        gemm128_body(hs, Wkv, kv, 2 * EKVv, Ee, (b >> 2) * 128, (b & 3) * 128, As, Bs);
    } else if (blk < 448) {
        int b = blk - 192;
        skinny_body(pe, Wpos, tk, EKVv, Ee, b >> 1, (b & 1) * 128);
    } else {
        int b = blk - 448;
        skinny_body(ce, Wchan, ck, EKVv, Ee, b >> 1, (b & 1) * 128);
    }
}

// ---------------- standalone GEMM for the output projection ------------------
__global__ __launch_bounds__(256) void sgemm128(
        const float* __restrict__ A, const float* __restrict__ B,
        float* __restrict__ Cmat, int N, int K) {
    __shared__ float As[2][8][128];
    __shared__ float Bs[2][8][128];
    gemm128_body(A, B, Cmat, N, K, blockIdx.y * 128, blockIdx.x * 128, As, Bs);
}

// ---------------- merged time_att + chan_att ---------------------------------
__global__ __launch_bounds__(256) void rel_att_kernel(
        const float* __restrict__ q, const float* __restrict__ bias) {
    __shared__ float qs[32][65];
    __shared__ float ks[128][64];
    int blk = blockIdx.x;
    int tid = threadIdx.x;
    if (blk < 1024) {
        int bh = blk & 31;
        int b = bh / Hh, h = bh % Hh, kvh = h / Gg;
        int t0 = (blk >> 5) * 32;
        for (int i = tid; i < 32 * 64; i += 256) {
            int r = i >> 6, d = i & 63;
            qs[r][d] = q[((size_t)(b * Tt + t0 + r)) * Ee + h * Dd + d]
                     + bias[EKVv + kvh * Dd + d];
        }
        for (int i = tid; i < 128 * 64; i += 256) {
            int p = i >> 6, d = i & 63;
            ks[p][d] = g_tk[p * EKVv + kvh * Dd + d];
        }
        __syncthreads();
        int r = tid & 31;
        int pb = (tid >> 5) * 16;
        float acc[16];
#pragma unroll
        for (int j = 0; j < 16; j++) acc[j] = 0.f;
        for (int d = 0; d < 64; d++) {
            float qv = qs[r][d];
#pragma unroll
            for (int j = 0; j < 16; j++) acc[j] += qv * ks[pb + j][d];
        }
        float* dst = g_time + ((size_t)bh * Tt + t0 + r) * Pp + pb;
#pragma unroll
        for (int j = 0; j < 16; j++) dst[j] = acc[j];
    } else {
        int bc = blk - 1024;
        int bh = bc & 31;
        int b = bh / Hh, h = bh % Hh, kvh = h / Gg;
        int t0 = (bc >> 5) * 32;
        for (int i = tid; i < 32 * 64; i += 256) {
            int r = i >> 6, d = i & 63;
            qs[r][d] = q[((size_t)(b * Tt + t0 + r)) * Ee + h * Dd + d]
                     + bias[2 * EKVv + kvh * Dd + d];
        }
        for (int i = tid; i < 8 * 64; i += 256) {
            int c = i >> 6, d = i & 63;
            ks[c][d] = g_ck[c * EKVv + kvh * Dd + d];
        }
        __syncthreads();
        int r = tid >> 3, c = tid & 7;
        float acc = 0.f;
#pragma unroll
        for (int d = 0; d < 64; d++) acc += qs[r][d] * ks[c][d];
        g_chan[((size_t)bh * Tt + t0 + r) * Cc + c] = acc;
    }
}

// ---------------- attention core: one block per (b, h, pt) -------------------
__global__ __launch_bounds__(256) void attn_kernel(
        const float* __restrict__ q, const float* __restrict__ bias) {
    __shared__ float qg[8][65];
    __shared__ float lg[8][1025];
    __shared__ float rinv[8];
    __shared__ float sred[8][8][64];
    int blk = blockIdx.x;
    int pt = (Pp - 1) - (blk % Pp);              // big-S blocks first
    int h  = (blk / Pp) % Hh;
    int b  = blk / (Pp * Hh);
    int kvh = h / Gg;
    int tid = threadIdx.x;
    int t0 = pt * Cc;

    for (int i = tid; i < 8 * 64; i += 256) {
        int c = i >> 6, d = i & 63;
        qg[c][d] = q[((size_t)(b * Tt + t0 + c)) * Ee + h * Dd + d]
                 + bias[kvh * Dd + d];
    }
    __syncthreads();

    int S = (pt + 1) * Cc;
    const float* tbase = g_time + (size_t)(b * Hh + h) * Tt * Pp;
    const float* cbase = g_chan + (size_t)(b * Hh + h) * Tt * Cc;

    // base logits, s-fastest mapping: lane-consecutive s0 -> coalesced tbase
    for (int s0 = tid; s0 < S; s0 += 256) {
        int ps = s0 >> 3, cs = s0 & 7;
#pragma unroll
        for (int c = 0; c < 8; c++) {
            int t = t0 + c;
            unsigned m = (unsigned)(t + 1) * Pp + ps;
            unsigned i2 = m / (Tt + 1);
            float tv = 0.f;
            if (m - i2 * (Tt + 1) != 0) tv = tbase[m - i2 - 1];
            int dc = c - cs; dc = dc < 0 ? -dc : dc;
            float cv = cbase[t * Cc + (Cc - 1 - dc)];
            lg[c][s0] = tv + cv;
        }
    }
    __syncthreads();

    // global term only inside the wm band (last patch row: everywhere)
    int gLow = (pt == Pp - 1) ? 0 : ((pt > 10 ? pt - 10 : 0) * Cc);
    int nG = (S - gLow) * 8;
    for (int idx = tid; idx < nG; idx += 256) {
        int s = gLow + (idx >> 3);
        int c = idx & 7;
        const float4* gk4 = (const float4*)(g_kv
            + ((size_t)(b * Tt + s)) * (2 * EKVv) + kvh * Dd);
        float acc = 0.f;
#pragma unroll
        for (int d4 = 0; d4 < 16; d4++) {
            float4 gv = gk4[d4];
            acc += qg[c][d4 * 4 + 0] * gv.x + qg[c][d4 * 4 + 1] * gv.y
                 + qg[c][d4 * 4 + 2] * gv.z + qg[c][d4 * 4 + 3] * gv.w;
        }
        lg[c][s] += acc;
    }
    __syncthreads();

    // softmax: warp w owns row w
    int w = tid >> 5, lane = tid & 31;
    {
        float mx = -1e30f;
        for (int s = lane; s < S; s += 32) mx = fmaxf(mx, lg[w][s] * 0.125f);
#pragma unroll
        for (int o = 16; o > 0; o >>= 1)
            mx = fmaxf(mx, __shfl_xor_sync(0xffffffffu, mx, o));
        float sum = 0.f;
        for (int s = lane; s < S; s += 32) {
            float e = __expf(lg[w][s] * 0.125f - mx);
            lg[w][s] = e;
            sum += e;
        }
#pragma unroll
        for (int o = 16; o > 0; o >>= 1)
            sum += __shfl_xor_sync(0xffffffffu, sum, o);
        if (lane == 0) rinv[w] = 1.f / sum;
    }
    __syncthreads();

    // out[c,d] = sum_s w[c,s]*v[s,d]; v loaded once per (s, d-pair)
    {
        int dp = (tid & 31) * 2;
        int sg = tid >> 5;
        const float* vbase = g_kv + (size_t)b * Tt * (2 * EKVv) + EKVv
                           + kvh * Dd + dp;
        float accx[8], accy[8];
#pragma unroll
        for (int c = 0; c < 8; c++) { accx[c] = 0.f; accy[c] = 0.f; }
        for (int s = sg; s < S; s += 8) {
            float2 vv = *(const float2*)(vbase + (size_t)s * (2 * EKVv));
#pragma unroll
            for (int c = 0; c < 8; c++) {
                float wgt = lg[c][s];
                accx[c] += wgt * vv.x;
                accy[c] += wgt * vv.y;
            }
        }
#pragma unroll
        for (int c = 0; c < 8; c++) {
            sred[sg][c][dp]     = accx[c];
            sred[sg][c][dp + 1] = accy[c];
        }
    }
    __syncthreads();
    for (int i = tid; i < 512; i += 256) {
        int c = i >> 6, dd = i & 63;
        float o = ((sred[0][c][dd] + sred[1][c][dd])
                 + (sred[2][c][dd] + sred[3][c][dd]))
                + ((sred[4][c][dd] + sred[5][c][dd])
                 + (sred[6][c][dd] + sred[7][c][dd]));
        g_ao[((size_t)(b * Tt + t0 + c)) * Ee + h * Dd + dd] = o * rinv[c];
    }
}

// ---------------- launch ----------------------------------------------------
extern "C" void kernel_launch(void* const* d_in, const int* in_sizes, int n_in,
                              void* d_out, int out_size) {
    const float* hs    = (const float*)d_in[0];
    const float* pe    = (const float*)d_in[1];
    const float* ce    = (const float*)d_in[2];
    const float* Wq    = (const float*)d_in[3];
    const float* Wkv   = (const float*)d_in[4];
    const float* Wpos  = (const float*)d_in[5];
    const float* Wchan = (const float*)d_in[6];
    const float* Wproj = (const float*)d_in[7];
    const float* bias  = (const float*)d_in[8];

    float *q, *kv, *tk, *ck, *ao;
    cudaGetSymbolAddress((void**)&q,  g_q);
    cudaGetSymbolAddress((void**)&kv, g_kv);
    cudaGetSymbolAddress((void**)&tk, g_tk);
    cudaGetSymbolAddress((void**)&ck, g_ck);
    cudaGetSymbolAddress((void**)&ao, g_ao);

    // all projections in one chip-filling launch
    mega_gemm<<<464, 256>>>(hs, Wq, Wkv, pe, Wpos, ce, Wchan, q, kv, tk, ck);

    // relative logits (time + chan merged)
    rel_att_kernel<<<2048, 256>>>(q, bias);

    // attention core
    attn_kernel<<<Bb * Hh * Pp, 256>>>(q, bias);

    // output projection -> d_out
    sgemm128<<<dim3(Ee / 128, (Bb * Tt) / 128), 256>>>(ao, Wproj, (float*)d_out, Ee, Ee);
}